// round 13
// baseline (speedup 1.0000x reference)
#include <cuda_runtime.h>
#include <math.h>

#define SEQ 16384
#define NGC 1536          // gate cols computed (f-gate skipped)
#define TT 20
#define NEGV -10000.0f
#define START_T 18
#define STOP_T 19

typedef unsigned int u32;

// ---------------- scratch (device globals, allocation-free) ----------------
__device__ float g_gates[(size_t)SEQ * NGC];              // 100.7 MB
__device__ float g_enc[(size_t)SEQ * 512];                // 33.6 MB
__device__ float g_feats[(size_t)SEQ * TT];               // 1.31 MB
__device__ unsigned char g_bp[(size_t)SEQ * TT];          // 327 KB
__device__ unsigned char g_cand[(size_t)128 * TT * 128];  // 327 KB
__device__ unsigned char g_map[128 * TT];
__device__ int g_ent[128];
__device__ int g_best;

// ---------------- K1: gate GEMM  G[m][n], n-layout [i_f|g_f|o_f|i_b|g_b|o_b] ----
__global__ void __launch_bounds__(256, 2) k_gemm(
    const float* __restrict__ X,   // tok base: x + 768
    const float* __restrict__ Wf,
    const float* __restrict__ Wb)
{
    __shared__ float As[16][128];
    __shared__ float Bs[16][128];

    const int tid = threadIdx.x;
    const int m0 = blockIdx.y * 128;
    const int n0 = blockIdx.x * 128;
    const int tx = tid & 15;
    const int ty = tid >> 4;

    // per-thread global-load slots: idx = tid + u*256  (u=0,1)
    const float* aptr[2];
    const float* bptr[2];
    int arow[2], akq[2], bcol[2], bkq[2];
#pragma unroll
    for (int u = 0; u < 2; u++) {
        int idx = tid + u * 256;        // 0..511
        arow[u] = idx >> 2;             // 0..127
        akq[u]  = idx & 3;              // float4 slot along k
        aptr[u] = X + (size_t)(m0 + arow[u]) * 768 + akq[u] * 4;
        bcol[u] = idx >> 2;
        bkq[u]  = idx & 3;
        int n = n0 + bcol[u];
        int dir = (n >= 768) ? 1 : 0;
        int mm = n - dir * 768;
        int row = mm + ((mm >= 256) ? 256 : 0);  // i:[0,256) g:[512,768) o:[768,1024)
        const float* wsrc = dir ? Wb : Wf;
        bptr[u] = wsrc + (size_t)row * 768 + bkq[u] * 4;
    }

    float acc[2][2][4][4];
#pragma unroll
    for (int a = 0; a < 2; a++)
#pragma unroll
        for (int b = 0; b < 2; b++)
#pragma unroll
            for (int r = 0; r < 4; r++)
#pragma unroll
                for (int c = 0; c < 4; c++) acc[a][b][r][c] = 0.0f;

    for (int kt = 0; kt < 48; kt++) {
        float4 av[2], bv[2];
#pragma unroll
        for (int u = 0; u < 2; u++) {
            av[u] = *(const float4*)(aptr[u] + kt * 16);
            bv[u] = *(const float4*)(bptr[u] + kt * 16);
        }
        __syncthreads();
#pragma unroll
        for (int u = 0; u < 2; u++) {
            As[akq[u] * 4 + 0][arow[u]] = av[u].x;
            As[akq[u] * 4 + 1][arow[u]] = av[u].y;
            As[akq[u] * 4 + 2][arow[u]] = av[u].z;
            As[akq[u] * 4 + 3][arow[u]] = av[u].w;
            Bs[bkq[u] * 4 + 0][bcol[u]] = bv[u].x;
            Bs[bkq[u] * 4 + 1][bcol[u]] = bv[u].y;
            Bs[bkq[u] * 4 + 2][bcol[u]] = bv[u].z;
            Bs[bkq[u] * 4 + 3][bcol[u]] = bv[u].w;
        }
        __syncthreads();
#pragma unroll
        for (int k = 0; k < 16; k++) {
            float4 a0 = *(const float4*)&As[k][ty * 4];
            float4 a1 = *(const float4*)&As[k][64 + ty * 4];
            float4 b0 = *(const float4*)&Bs[k][tx * 4];
            float4 b1 = *(const float4*)&Bs[k][64 + tx * 4];
            const float ar[2][4] = {{a0.x, a0.y, a0.z, a0.w}, {a1.x, a1.y, a1.z, a1.w}};
            const float br[2][4] = {{b0.x, b0.y, b0.z, b0.w}, {b1.x, b1.y, b1.z, b1.w}};
#pragma unroll
            for (int rg = 0; rg < 2; rg++)
#pragma unroll
                for (int r = 0; r < 4; r++)
#pragma unroll
                    for (int cg = 0; cg < 2; cg++)
#pragma unroll
                        for (int c = 0; c < 4; c++)
                            acc[rg][cg][r][c] = fmaf(ar[rg][r], br[cg][c], acc[rg][cg][r][c]);
        }
    }

#pragma unroll
    for (int rg = 0; rg < 2; rg++)
#pragma unroll
        for (int r = 0; r < 4; r++) {
            int gm = m0 + rg * 64 + ty * 4 + r;
            float* out = g_gates + (size_t)gm * NGC + n0;
#pragma unroll
            for (int cg = 0; cg < 2; cg++) {
                float4 v = make_float4(acc[rg][cg][r][0], acc[rg][cg][r][1],
                                       acc[rg][cg][r][2], acc[rg][cg][r][3]);
                *(float4*)(out + cg * 64 + tx * 4) = v;
            }
        }
}

// ---------------- K2: activations -> enc ----------------
__global__ void k_act(const float* __restrict__ bihf, const float* __restrict__ bhhf,
                      const float* __restrict__ bihb, const float* __restrict__ bhhb)
{
    int idx = blockIdx.x * blockDim.x + threadIdx.x;
    if (idx >= SEQ * 512) return;
    int m = idx >> 9;
    int c = idx & 511;
    int dir = c >> 8;
    int ch = c & 255;
    const float* G = g_gates + (size_t)m * NGC + dir * 768;
    const float* bi = dir ? bihb : bihf;
    const float* bh = dir ? bhhb : bhhf;
    float gi = (G[ch]        + bi[ch])        + bh[ch];
    float gg = (G[256 + ch]  + bi[512 + ch])  + bh[512 + ch];
    float go = (G[512 + ch]  + bi[768 + ch])  + bh[768 + ch];
    float si = 1.0f / (1.0f + expf(-gi));
    float so = 1.0f / (1.0f + expf(-go));
    float cc = si * tanhf(gg);
    g_enc[(size_t)m * 512 + c] = so * tanhf(cc);
}

// ---------------- K3: feats = enc @ w_tag.T + b_tag ----------------
__global__ void __launch_bounds__(256) k_feats(const float* __restrict__ Wt,
                                               const float* __restrict__ bt)
{
    __shared__ float es[64][68];
    __shared__ float ws[20][68];
    const int tid = threadIdx.x;
    const int m0 = blockIdx.x * 64;
    float acc[5] = {0.f, 0.f, 0.f, 0.f, 0.f};

    for (int kc = 0; kc < 512; kc += 64) {
        __syncthreads();
#pragma unroll
        for (int u = 0; u < 4; u++) {
            int idx = tid + u * 256;            // 0..1023 float4 slots
            int row = idx >> 4, kq = idx & 15;
            float4 v = *(const float4*)(g_enc + (size_t)(m0 + row) * 512 + kc + kq * 4);
            *(float4*)&es[row][kq * 4] = v;
        }
#pragma unroll
        for (int u = 0; u < 2; u++) {
            int idx = tid + u * 256;
            if (idx < 320) {                    // 20*16 float4 slots
                int row = idx >> 4, kq = idx & 15;
                float4 v = *(const float4*)(Wt + (size_t)row * 512 + kc + kq * 4);
                *(float4*)&ws[row][kq * 4] = v;
            }
        }
        __syncthreads();
#pragma unroll
        for (int q = 0; q < 5; q++) {
            int o = tid * 5 + q;
            int tok = o / 20, tag = o % 20;
            float a = acc[q];
#pragma unroll
            for (int k = 0; k < 64; k++) a = fmaf(es[tok][k], ws[tag][k], a);
            acc[q] = a;
        }
    }
#pragma unroll
    for (int q = 0; q < 5; q++) {
        int o = tid * 5 + q;
        int tok = o / 20, tag = o % 20;
        g_feats[(size_t)(m0 + tok) * TT + tag] = acc[q] + bt[tag];
    }
}

// ---------------- K4: serial Viterbi forward (1 warp) ----------------
__device__ __forceinline__ float vstep(float fv, const float tr[TT], float feat,
                                       int t, int j, bool act)
{
    float ss[TT];
    int ii[TT];
#pragma unroll
    for (int i = 0; i < TT; i++) {
        float v = __shfl_sync(0xffffffffu, fv, i);
        ss[i] = v + tr[i];
        ii[i] = i;
    }
#define CMB(d, a, b) { bool p = ss[b] > ss[a]; ss[d] = p ? ss[b] : ss[a]; ii[d] = p ? ii[b] : ii[a]; }
#pragma unroll
    for (int q = 0; q < 10; q++) CMB(q, 2 * q, 2 * q + 1);   // 20 -> 10
#pragma unroll
    for (int q = 0; q < 5; q++)  CMB(q, 2 * q, 2 * q + 1);   // 10 -> 5
    CMB(0, 0, 1); CMB(1, 2, 3); ss[2] = ss[4]; ii[2] = ii[4]; // 5 -> 3
    CMB(0, 0, 1); ss[1] = ss[2]; ii[1] = ii[2];               // 3 -> 2
    CMB(0, 0, 1);                                             // 2 -> 1
#undef CMB
    if (act) g_bp[(size_t)t * TT + j] = (unsigned char)ii[0];
    return ss[0] + feat;
}

__global__ void k_vit(const float* __restrict__ trans, float* __restrict__ out, int off)
{
    const int j = threadIdx.x;
    const bool act = (j < TT);
    float tr[TT];
#pragma unroll
    for (int i = 0; i < TT; i++) tr[i] = act ? trans[j * TT + i] : NEGV;
    float fv = (j == START_T) ? 0.0f : NEGV;

#define LDF(t) (act ? __ldg(&g_feats[(size_t)(t) * TT + j]) : 0.0f)
    float f0 = LDF(0), f1 = LDF(1), f2 = LDF(2), f3 = LDF(3);
    for (int t = 0; t < SEQ; t += 4) {
        int p = (t + 4 < SEQ) ? (t + 4) : (SEQ - 4);
        float n0 = LDF(p + 0), n1 = LDF(p + 1), n2 = LDF(p + 2), n3 = LDF(p + 3);
        fv = vstep(fv, tr, f0, t + 0, j, act);
        fv = vstep(fv, tr, f1, t + 1, j, act);
        fv = vstep(fv, tr, f2, t + 2, j, act);
        fv = vstep(fv, tr, f3, t + 3, j, act);
        f0 = n0; f1 = n1; f2 = n2; f3 = n3;
    }
#undef LDF

    float term = act ? (fv + trans[STOP_T * TT + j]) : NEGV;
    float best = NEGV * 4.0f;
    int bj = 0;
#pragma unroll
    for (int i = 0; i < TT; i++) {
        float v = __shfl_sync(0xffffffffu, term, i);
        if (v > best) { best = v; bj = i; }
    }
    if (j == 0) {
        g_best = bj;
        if (off) out[0] = best;
    }
}

// ---------------- K5: backtrack phase A (chunk candidates + maps) ----------------
__global__ void k_bt1()
{
    __shared__ unsigned char bl[128 * TT];
    const int c = blockIdx.x;
    const int t0 = c * 128;
    const u32* src = (const u32*)(g_bp + (size_t)t0 * TT);
    u32* dst = (u32*)bl;
    for (int i = threadIdx.x; i < 640; i += 32) dst[i] = src[i];
    __syncwarp();
    int s = threadIdx.x;
    if (s < TT) {
        int cur = s;
        unsigned char* cand = g_cand + ((size_t)c * TT + s) * 128;
        cand[127] = (unsigned char)cur;
        for (int r = 127; r >= 1; r--) {
            cur = bl[r * TT + cur];
            cand[r - 1] = (unsigned char)cur;
        }
        g_map[c * TT + s] = bl[cur];  // exit state = bp[t0][s_{t0}]
    }
}

// ---------------- K6: backtrack phase B (serial chunk stitch) ----------------
__global__ void k_bt2()
{
    __shared__ unsigned char mp[128 * TT];
    u32* dst = (u32*)mp;
    const u32* src = (const u32*)g_map;
    for (int i = threadIdx.x; i < 640; i += 32) dst[i] = src[i];
    __syncwarp();
    if (threadIdx.x == 0) {
        int e = g_best;
        g_ent[127] = e;
        for (int c = 127; c >= 1; c--) {
            e = mp[c * TT + e];
            g_ent[c - 1] = e;
        }
    }
}

// ---------------- K7: backtrack phase C (emit path) ----------------
__global__ void k_bt3(float* __restrict__ out, int off)
{
    int c = blockIdx.x, r = threadIdx.x;
    int e = g_ent[c];
    out[off + c * 128 + r] = (float)g_cand[((size_t)c * TT + e) * 128 + r];
}

// ---------------- launcher ----------------
extern "C" void kernel_launch(void* const* d_in, const int* in_sizes, int n_in,
                              void* d_out, int out_size)
{
    const float* x     = (const float*)d_in[0];
    const float* wihf  = (const float*)d_in[1];
    const float* bihf  = (const float*)d_in[3];
    const float* bhhf  = (const float*)d_in[4];
    const float* wihb  = (const float*)d_in[5];
    const float* bihb  = (const float*)d_in[7];
    const float* bhhb  = (const float*)d_in[8];
    const float* wtag  = (const float*)d_in[9];
    const float* btag  = (const float*)d_in[10];
    const float* trans = (const float*)d_in[11];
    float* out = (float*)d_out;

    int off = (out_size >= SEQ + 1) ? 1 : 0;

    dim3 gg(NGC / 128, SEQ / 128);
    k_gemm<<<gg, 256>>>(x + 768, wihf, wihb);
    k_act<<<(SEQ * 512) / 256, 256>>>(bihf, bhhf, bihb, bhhb);
    k_feats<<<SEQ / 64, 256>>>(wtag, btag);
    k_vit<<<1, 32>>>(trans, out, off);
    k_bt1<<<128, 32>>>();
    k_bt2<<<1, 32>>>();
    k_bt3<<<128, 128>>>(out, off);
}